// round 13
// baseline (speedup 1.0000x reference)
#include <cuda_runtime.h>
#include <cstdint>

// Problem constants (fixed shapes for this problem instance)
#define GN   100000      // nodes
#define GE   1600000     // edges
#define GEL  200000      // link-pred edges
#define INC  64
#define POSC 16
#define KH   80          // INC + POSC
#define HID  64
#define OUTC 32
#define NB   98          // scan blocks: ceil(GN / 1024)

typedef unsigned long long ull;

// ---------------- packed f32x2 helpers (sm_103a FFMA2 path) ------------------
__device__ __forceinline__ void ffma2(ull& d, ull a, ull b) {
    asm("fma.rn.f32x2 %0, %1, %2, %0;" : "+l"(d) : "l"(a), "l"(b));
}
__device__ __forceinline__ ull splat2(float v) {
    ull r; asm("mov.b64 %0, {%1, %1};" : "=l"(r) : "f"(v)); return r;
}
__device__ __forceinline__ float2 unpk2(ull v) {
    float2 f; asm("mov.b64 {%0, %1}, %2;" : "=f"(f.x), "=f"(f.y) : "l"(v)); return f;
}

// ---------------- scratch (device globals; no allocation allowed) -----------
__device__ float g_dinv[GN];
__device__ float g_hw1 [GN * HID];
__device__ float g_agg1[GN * HID];
__device__ float g_hw2 [GN * OUTC];
__device__ float g_wa  [GN];
__device__ float g_wb  [GN];
__device__ int   g_cnt [GN];        // incoming-degree (no self-loop)
__device__ int   g_cur [GN];        // scatter cursor
__device__ int   g_bsum[128];
__device__ int   g_bscan[128];
__device__ int   g_csrc[GE];        // dst-sorted edge list: src
__device__ int   g_cdst[GE];        // dst-sorted edge list: dst
__device__ float g_cnrm[GE];        // dst-sorted edge list: dinv[s]*dinv[d]

// ---------------- degree histogram ------------------------------------------
__global__ void k_zero_cnt(int* cnt) {
    int i = blockIdx.x * blockDim.x + threadIdx.x;
    if (i < GN) cnt[i] = 0;
}

__global__ void k_hist(const int* __restrict__ dst, int* cnt) {
    int i = blockIdx.x * blockDim.x + threadIdx.x;
    if (i < GE) atomicAdd(&cnt[dst[i]], 1);
}

// ---------------- exclusive scan of cnt -> cur (3 kernels) ------------------
__global__ void k_scan_local(const int* __restrict__ cnt, int* off, int* bsum) {
    __shared__ int s[256];
    const int b = blockIdx.x, t = threadIdx.x;
    const int i0 = b * 1024 + t * 4;
    int v[4]; int sum = 0;
#pragma unroll
    for (int j = 0; j < 4; j++) {
        int idx = i0 + j;
        int c = (idx < GN) ? cnt[idx] : 0;
        v[j] = sum; sum += c;
    }
    s[t] = sum;
    __syncthreads();
    for (int d = 1; d < 256; d <<= 1) {
        int x = (t >= d) ? s[t - d] : 0;
        __syncthreads();
        s[t] += x;
        __syncthreads();
    }
    int base = (t > 0) ? s[t - 1] : 0;
#pragma unroll
    for (int j = 0; j < 4; j++) {
        int idx = i0 + j;
        if (idx < GN) off[idx] = base + v[j];
    }
    if (t == 255) bsum[b] = s[255];
}

__global__ void k_scan_bsum(const int* __restrict__ bsum, int* bscan) {
    __shared__ int s[128];
    int t = threadIdx.x;
    s[t] = (t < NB) ? bsum[t] : 0;
    __syncthreads();
    for (int d = 1; d < 128; d <<= 1) {
        int x = (t >= d) ? s[t - d] : 0;
        __syncthreads();
        s[t] += x;
        __syncthreads();
    }
    if (t < NB) bscan[t] = (t > 0) ? s[t - 1] : 0;
}

// scan finalize + dinv fused (one fewer launch in serial build chain)
__global__ void k_scan_add(int* cur, const int* __restrict__ bscan,
                           const int* __restrict__ cnt, float* dinv) {
    const int b = blockIdx.x, t = threadIdx.x;
    const int add = bscan[b];
    const int i0 = b * 1024 + t * 4;
#pragma unroll
    for (int j = 0; j < 4; j++) {
        int idx = i0 + j;
        if (idx < GN) {
            cur[idx] += add;
            dinv[idx] = rsqrtf((float)(cnt[idx] + 1));   // +1 self-loop
        }
    }
}

// ---------------- fill dst-sorted edge list ----------------------------------
__global__ void k_fill(const int* __restrict__ src, const int* __restrict__ dst,
                       const float* __restrict__ dinv,
                       int* cur, int* csrc, int* cdst, float* cnrm) {
    int e = blockIdx.x * blockDim.x + threadIdx.x;
    if (e >= GE) return;
    int s = __ldg(&src[e]);
    int d = __ldg(&dst[e]);
    int p = atomicAdd(&cur[d], 1);
    csrc[p] = s;
    cdst[p] = d;
    cnrm[p] = __ldg(&dinv[s]) * __ldg(&dinv[d]);
}

// ---------------- GEMM 1: hw1 = [x | pos] @ W1  (K=80, Nout=64) -------------
// 64 rows per block, 256 threads (8 warps -> 40 warps/SM). Thread: 2 rows x
// 8 cols via 4 packed f32x2 accumulators per row (FFMA2).
#define KHP  81
#define G1_ROWS 64
__global__ __launch_bounds__(256) void k_gemm1(
    const float* __restrict__ x, const float* __restrict__ pos,
    const float* __restrict__ W1, float* __restrict__ hw1)
{
    __shared__ __align__(16) float sW[KH * HID];          // 20 KB, 16B-aligned
    __shared__ __align__(16) float sX[G1_ROWS * KHP];     // 20.7 KB
    const int t = threadIdx.x;
    const int row0 = blockIdx.x * G1_ROWS;

    for (int i = t; i < KH * HID; i += 256) sW[i] = W1[i];
    for (int i = t; i < G1_ROWS * INC; i += 256) {
        int r = i >> 6, c = i & 63;
        int gr = row0 + r;
        sX[r * KHP + c] = (gr < GN) ? x[gr * INC + c] : 0.0f;
    }
    for (int i = t; i < G1_ROWS * POSC; i += 256) {
        int r = i >> 4, c = i & 15;
        int gr = row0 + r;
        sX[r * KHP + INC + c] = (gr < GN) ? pos[gr * POSC + c] : 0.0f;
    }
    __syncthreads();

    const int tx = t & 7;    // 8 col groups x 8 cols = 64
    const int ty = t >> 3;   // 32 row groups x 2 rows = 64
    ull acc[2][4];
#pragma unroll
    for (int r = 0; r < 2; r++)
#pragma unroll
        for (int c = 0; c < 4; c++) acc[r][c] = 0ull;

#pragma unroll 4
    for (int k = 0; k < KH; k++) {
        ulonglong2 wA = *(const ulonglong2*)&sW[k * HID + tx * 8];
        ulonglong2 wB = *(const ulonglong2*)&sW[k * HID + tx * 8 + 4];
#pragma unroll
        for (int r = 0; r < 2; r++) {
            ull xx = splat2(sX[(ty * 2 + r) * KHP + k]);
            ffma2(acc[r][0], xx, wA.x);
            ffma2(acc[r][1], xx, wA.y);
            ffma2(acc[r][2], xx, wB.x);
            ffma2(acc[r][3], xx, wB.y);
        }
    }

#pragma unroll
    for (int r = 0; r < 2; r++) {
        int gr = row0 + ty * 2 + r;
        if (gr < GN) {
            float2 c0 = unpk2(acc[r][0]), c1 = unpk2(acc[r][1]);
            float2 c2 = unpk2(acc[r][2]), c3 = unpk2(acc[r][3]);
            *(float4*)&hw1[gr * HID + tx * 8]     = make_float4(c0.x, c0.y, c1.x, c1.y);
            *(float4*)&hw1[gr * HID + tx * 8 + 4] = make_float4(c2.x, c2.y, c3.x, c3.y);
        }
    }
}

// ---------------- layer-1 agg init: agg1 = b1 + hw1 * dinv^2 ----------------
__global__ void k_init1(const float4* __restrict__ hw, float4* __restrict__ out,
                        const float* __restrict__ b1, const float* __restrict__ dinv)
{
    int i = blockIdx.x * blockDim.x + threadIdx.x;
    if (i >= GN * 16) return;
    int node = i >> 4, q = i & 15;
    float dv = __ldg(&dinv[node]);
    float s = dv * dv;
    float4 v = __ldg(&hw[i]);
    float4 b = __ldg(&((const float4*)b1)[q]);
    out[i] = make_float4(b.x + v.x * s, b.y + v.y * s,
                         b.z + v.z * s, b.w + v.w * s);
}

// ---------------- GEMM 2: hw2 = relu(agg1) @ W2  (K=64, Nout=32) ------------
// 128 rows per block, 256 threads. Thread: 2 rows x 8 cols (FFMA2).
// Epilogue writes z = b2 + hw2 * dinv^2 (dinv ready by now).
#define HIDP 65
#define G2_ROWS 128
__global__ __launch_bounds__(256) void k_gemm2(
    const float* __restrict__ h, const float* __restrict__ W2,
    const float* __restrict__ b2, const float* __restrict__ dinv,
    float* __restrict__ hw2, float* __restrict__ z)
{
    __shared__ __align__(16) float sW[HID * OUTC];        // 8 KB, 16B-aligned
    __shared__ __align__(16) float sH[G2_ROWS * HIDP];    // 33.3 KB
    const int t = threadIdx.x;
    const int row0 = blockIdx.x * G2_ROWS;

    for (int i = t; i < HID * OUTC; i += 256) sW[i] = W2[i];
    for (int i = t; i < G2_ROWS * HID; i += 256) {
        int r = i >> 6, c = i & 63;
        int gr = row0 + r;
        float v = (gr < GN) ? h[gr * HID + c] : 0.0f;
        sH[r * HIDP + c] = v > 0.0f ? v : 0.0f;       // fused ReLU
    }
    __syncthreads();

    const int tx = t & 3;    // 4 col groups x 8 cols = 32
    const int ty = t >> 2;   // 64 row groups x 2 rows = 128
    ull acc[2][4];
#pragma unroll
    for (int r = 0; r < 2; r++)
#pragma unroll
        for (int c = 0; c < 4; c++) acc[r][c] = 0ull;

#pragma unroll 4
    for (int k = 0; k < HID; k++) {
        ulonglong2 wA = *(const ulonglong2*)&sW[k * OUTC + tx * 8];
        ulonglong2 wB = *(const ulonglong2*)&sW[k * OUTC + tx * 8 + 4];
#pragma unroll
        for (int r = 0; r < 2; r++) {
            ull hv = splat2(sH[(ty * 2 + r) * HIDP + k]);
            ffma2(acc[r][0], hv, wA.x);
            ffma2(acc[r][1], hv, wA.y);
            ffma2(acc[r][2], hv, wB.x);
            ffma2(acc[r][3], hv, wB.y);
        }
    }

    float4 bA = __ldg(&((const float4*)b2)[tx * 2]);
    float4 bB = __ldg(&((const float4*)b2)[tx * 2 + 1]);
#pragma unroll
    for (int r = 0; r < 2; r++) {
        int gr = row0 + ty * 2 + r;
        if (gr < GN) {
            float dv = __ldg(&dinv[gr]);
            float s = dv * dv;
            float2 c0 = unpk2(acc[r][0]), c1 = unpk2(acc[r][1]);
            float2 c2 = unpk2(acc[r][2]), c3 = unpk2(acc[r][3]);
            *(float4*)&hw2[gr * OUTC + tx * 8]     = make_float4(c0.x, c0.y, c1.x, c1.y);
            *(float4*)&hw2[gr * OUTC + tx * 8 + 4] = make_float4(c2.x, c2.y, c3.x, c3.y);
            *(float4*)&z[gr * OUTC + tx * 8] =
                make_float4(bA.x + c0.x * s, bA.y + c0.y * s,
                            bA.z + c1.x * s, bA.w + c1.y * s);
            *(float4*)&z[gr * OUTC + tx * 8 + 4] =
                make_float4(bB.x + c2.x * s, bB.y + c2.y * s,
                            bB.z + c3.x * s, bB.w + c3.y * s);
        }
    }
}

// ---------------- segmented edge aggregation over dst-sorted list ------------
template <int LOGQ, int SB>   // LOGQ=4 (64 feats) SB=256 ; LOGQ=3 (32) SB=512
__global__ __launch_bounds__(256) void k_agg_seg(
    const float4* __restrict__ vals, float4* __restrict__ out,
    const int* __restrict__ csrc, const int* __restrict__ cdst,
    const float* __restrict__ cnrm)
{
    __shared__ int   ssrc[SB];
    __shared__ int   sdst[SB];
    __shared__ float snrm[SB];
    const int t = threadIdx.x;
    const int s0 = blockIdx.x * SB;
    for (int i = t; i < SB; i += 256) {
        ssrc[i] = csrc[s0 + i];
        sdst[i] = cdst[s0 + i];
        snrm[i] = cnrm[s0 + i];
    }
    __syncthreads();

    const int q    = t & ((1 << LOGQ) - 1);
    const int base = (t >> LOGQ) * 16;          // window of 16 slots

    int cur = sdst[base];
    float ax = 0.0f, ay = 0.0f, az = 0.0f, aw = 0.0f;
#pragma unroll
    for (int j = 0; j < 16; j++) {
        int sd = sdst[base + j];
        if (sd != cur) {
            float4* p = &out[(cur << LOGQ) + q];
            asm volatile("red.global.add.v4.f32 [%0], {%1,%2,%3,%4};"
                         :: "l"(p), "f"(ax), "f"(ay), "f"(az), "f"(aw)
                         : "memory");
            ax = ay = az = aw = 0.0f;
            cur = sd;
        }
        float nm = snrm[base + j];
        float4 v = __ldg(&vals[(ssrc[base + j] << LOGQ) + q]);
        ax += v.x * nm; ay += v.y * nm; az += v.z * nm; aw += v.w * nm;
    }
    float4* p = &out[(cur << LOGQ) + q];
    asm volatile("red.global.add.v4.f32 [%0], {%1,%2,%3,%4};"
                 :: "l"(p), "f"(ax), "f"(ay), "f"(az), "f"(aw)
                 : "memory");
}

// ---------------- link head: wa = z.Wl[0:32], wb = z.Wl[32:64] --------------
__global__ void k_wab(const float* __restrict__ z, const float* __restrict__ Wl,
                      float* __restrict__ wa, float* __restrict__ wb)
{
    __shared__ float sWl[2 * OUTC];
    int t = threadIdx.x;
    if (t < 2 * OUTC) sWl[t] = Wl[t];
    __syncthreads();
    int i = blockIdx.x * blockDim.x + t;
    if (i >= GN) return;
    const float4* zr = (const float4*)&z[i * OUTC];
    float a = 0.0f, b = 0.0f;
#pragma unroll
    for (int q = 0; q < OUTC / 4; q++) {
        float4 v = zr[q];
        a += v.x * sWl[q*4+0] + v.y * sWl[q*4+1] + v.z * sWl[q*4+2] + v.w * sWl[q*4+3];
        b += v.x * sWl[OUTC+q*4+0] + v.y * sWl[OUTC+q*4+1]
           + v.z * sWl[OUTC+q*4+2] + v.w * sWl[OUTC+q*4+3];
    }
    wa[i] = a; wb[i] = b;
}

__global__ void k_pred(const float* __restrict__ wa, const float* __restrict__ wb,
                       const int* __restrict__ sl, const int* __restrict__ dl,
                       const float* __restrict__ bl, float* __restrict__ pred)
{
    int i = blockIdx.x * blockDim.x + threadIdx.x;
    if (i >= GEL) return;
    pred[i] = wa[__ldg(&sl[i])] + wb[__ldg(&dl[i])] + bl[0];
}

// ---------------- launch -----------------------------------------------------
extern "C" void kernel_launch(void* const* d_in, const int* in_sizes, int n_in,
                              void* d_out, int out_size)
{
    const float* x    = (const float*)d_in[0];
    const float* pos  = (const float*)d_in[1];
    const float* W1   = (const float*)d_in[2];
    const float* b1   = (const float*)d_in[3];
    const float* W2   = (const float*)d_in[4];
    const float* b2   = (const float*)d_in[5];
    const float* Wl   = (const float*)d_in[6];
    const float* bl   = (const float*)d_in[7];
    const int*   ei   = (const int*)d_in[8];   // [2, E]: src row then dst row
    const int*   eli  = (const int*)d_in[9];   // [2, EL]

    const int* src = ei;
    const int* dst = ei + GE;
    const int* sl  = eli;
    const int* dl  = eli + GEL;

    float* z    = (float*)d_out;               // [N, OUTC]
    float* pred = z + (size_t)GN * OUTC;       // [EL]

    float *dinv, *hw1, *agg1, *hw2, *wa, *wb, *cnrm;
    int *cnt, *cur, *bsum, *bscan, *csrc, *cdst;
    cudaGetSymbolAddress((void**)&dinv,  g_dinv);
    cudaGetSymbolAddress((void**)&hw1,   g_hw1);
    cudaGetSymbolAddress((void**)&agg1,  g_agg1);
    cudaGetSymbolAddress((void**)&hw2,   g_hw2);
    cudaGetSymbolAddress((void**)&wa,    g_wa);
    cudaGetSymbolAddress((void**)&wb,    g_wb);
    cudaGetSymbolAddress((void**)&cnt,   g_cnt);
    cudaGetSymbolAddress((void**)&cur,   g_cur);
    cudaGetSymbolAddress((void**)&bsum,  g_bsum);
    cudaGetSymbolAddress((void**)&bscan, g_bscan);
    cudaGetSymbolAddress((void**)&csrc,  g_csrc);
    cudaGetSymbolAddress((void**)&cdst,  g_cdst);
    cudaGetSymbolAddress((void**)&cnrm,  g_cnrm);

    const int B = 256;

    // Fork: CSR build on a side stream, gemm1 (independent) on the main stream.
    // (Exact 2-event topology that passed in rounds 9 and 11.)
    cudaStream_t side;
    cudaStreamCreateWithFlags(&side, cudaStreamNonBlocking);
    cudaEvent_t evF, evJ;
    cudaEventCreateWithFlags(&evF, cudaEventDisableTiming);
    cudaEventCreateWithFlags(&evJ, cudaEventDisableTiming);

    cudaEventRecord(evF, 0);
    cudaStreamWaitEvent(side, evF, 0);

    // ---- side stream: histogram -> scan(+dinv) -> dst-sorted fill
    k_zero_cnt<<<(GN + B - 1) / B, B, 0, side>>>(cnt);
    k_hist<<<(GE + B - 1) / B, B, 0, side>>>(dst, cnt);
    k_scan_local<<<NB, 256, 0, side>>>(cnt, cur, bsum);
    k_scan_bsum<<<1, 128, 0, side>>>(bsum, bscan);
    k_scan_add<<<NB, 256, 0, side>>>(cur, bscan, cnt, dinv);
    k_fill<<<(GE + B - 1) / B, B, 0, side>>>(src, dst, dinv, cur, csrc, cdst, cnrm);
    cudaEventRecord(evJ, side);                 // build done

    // ---- main stream: gemm1 runs concurrently with the build
    k_gemm1<<<(GN + G1_ROWS - 1) / G1_ROWS, 256>>>(x, pos, W1, hw1);

    // Join: everything below needs the build outputs.
    cudaStreamWaitEvent(0, evJ, 0);

    // ---- layer 1
    k_init1<<<(GN * 16 + B - 1) / B, B>>>((const float4*)hw1, (float4*)agg1, b1, dinv);
    k_agg_seg<4, 256><<<GE / 256, 256>>>((const float4*)hw1, (float4*)agg1,
                                         csrc, cdst, cnrm);

    // ---- layer 2 (ReLU fused into gemm2 smem load; z init fused in epilogue)
    k_gemm2<<<(GN + G2_ROWS - 1) / G2_ROWS, 256>>>(agg1, W2, b2, dinv, hw2, z);
    k_agg_seg<3, 512><<<GE / 512, 256>>>((const float4*)hw2, (float4*)z,
                                         csrc, cdst, cnrm);

    // ---- link-prediction head: pred = z[s].Wl_top + z[d].Wl_bot + bl
    k_wab<<<(GN + B - 1) / B, B>>>(z, Wl, wa, wb);
    k_pred<<<(GEL + B - 1) / B, B>>>(wa, wb, sl, dl, bl, pred);
}

// round 14
// speedup vs baseline: 1.1528x; 1.1528x over previous
#include <cuda_runtime.h>
#include <cstdint>

// Problem constants (fixed shapes for this problem instance)
#define GN   100000      // nodes
#define GE   1600000     // edges
#define GEL  200000      // link-pred edges
#define INC  64
#define POSC 16
#define KH   80          // INC + POSC
#define HID  64
#define OUTC 32
#define NB   98          // scan blocks: ceil(GN / 1024)

// ---------------- scratch (device globals; no allocation allowed) -----------
__device__ float g_dinv[GN];
__device__ float g_hw1 [GN * HID];
__device__ float g_agg1[GN * HID];
__device__ float g_hw2 [GN * OUTC];
__device__ float g_wa  [GN];
__device__ float g_wb  [GN];
__device__ int   g_cnt [GN];        // incoming-degree (no self-loop)
__device__ int   g_cur [GN];        // scatter cursor
__device__ int   g_bsum[128];
__device__ int   g_bscan[128];
__device__ int   g_csrc[GE];        // dst-sorted edge list: src
__device__ int   g_cdst[GE];        // dst-sorted edge list: dst
__device__ float g_cnrm[GE];        // dst-sorted edge list: dinv[s]*dinv[d]

// component select (compile-time under full unroll)
__device__ __forceinline__ float f4c(const float4& v, int kk) {
    return kk == 0 ? v.x : kk == 1 ? v.y : kk == 2 ? v.z : v.w;
}

// ---------------- degree histogram ------------------------------------------
__global__ void k_zero_cnt(int* cnt) {
    int i = blockIdx.x * blockDim.x + threadIdx.x;
    if (i < GN) cnt[i] = 0;
}

__global__ void k_hist(const int* __restrict__ dst, int* cnt) {
    int i = blockIdx.x * blockDim.x + threadIdx.x;
    if (i < GE) atomicAdd(&cnt[dst[i]], 1);
}

// ---------------- exclusive scan of cnt -> cur (3 kernels) ------------------
__global__ void k_scan_local(const int* __restrict__ cnt, int* off, int* bsum) {
    __shared__ int s[256];
    const int b = blockIdx.x, t = threadIdx.x;
    const int i0 = b * 1024 + t * 4;
    int v[4]; int sum = 0;
#pragma unroll
    for (int j = 0; j < 4; j++) {
        int idx = i0 + j;
        int c = (idx < GN) ? cnt[idx] : 0;
        v[j] = sum; sum += c;
    }
    s[t] = sum;
    __syncthreads();
    for (int d = 1; d < 256; d <<= 1) {
        int x = (t >= d) ? s[t - d] : 0;
        __syncthreads();
        s[t] += x;
        __syncthreads();
    }
    int base = (t > 0) ? s[t - 1] : 0;
#pragma unroll
    for (int j = 0; j < 4; j++) {
        int idx = i0 + j;
        if (idx < GN) off[idx] = base + v[j];
    }
    if (t == 255) bsum[b] = s[255];
}

__global__ void k_scan_bsum(const int* __restrict__ bsum, int* bscan) {
    __shared__ int s[128];
    int t = threadIdx.x;
    s[t] = (t < NB) ? bsum[t] : 0;
    __syncthreads();
    for (int d = 1; d < 128; d <<= 1) {
        int x = (t >= d) ? s[t - d] : 0;
        __syncthreads();
        s[t] += x;
        __syncthreads();
    }
    if (t < NB) bscan[t] = (t > 0) ? s[t - 1] : 0;
}

// scan finalize + dinv fused (ran correctly in rounds 11/13)
__global__ void k_scan_add(int* cur, const int* __restrict__ bscan,
                           const int* __restrict__ cnt, float* dinv) {
    const int b = blockIdx.x, t = threadIdx.x;
    const int add = bscan[b];
    const int i0 = b * 1024 + t * 4;
#pragma unroll
    for (int j = 0; j < 4; j++) {
        int idx = i0 + j;
        if (idx < GN) {
            cur[idx] += add;
            dinv[idx] = rsqrtf((float)(cnt[idx] + 1));   // +1 self-loop
        }
    }
}

// ---------------- fill dst-sorted edge list ----------------------------------
__global__ void k_fill(const int* __restrict__ src, const int* __restrict__ dst,
                       const float* __restrict__ dinv,
                       int* cur, int* csrc, int* cdst, float* cnrm) {
    int e = blockIdx.x * blockDim.x + threadIdx.x;
    if (e >= GE) return;
    int s = __ldg(&src[e]);
    int d = __ldg(&dst[e]);
    int p = atomicAdd(&cur[d], 1);
    csrc[p] = s;
    cdst[p] = d;
    cnrm[p] = __ldg(&dinv[s]) * __ldg(&dinv[d]);
}

// ---------------- GEMM 1: hw1 = [x | pos] @ W1  (K=80, Nout=64) -------------
// 64 rows per block, 256 threads (40 warps/SM). Thread: 4 rows x 4 cols.
// k-loop in blocks of 4 with vectorized float4 operand loads (KHP mult of 4).
#define KHP  84          // padded row stride (mult of 4; 84 mod 32 banks = 20)
#define G1_ROWS 64
__global__ __launch_bounds__(256) void k_gemm1(
    const float* __restrict__ x, const float* __restrict__ pos,
    const float* __restrict__ W1, float* __restrict__ hw1)
{
    __shared__ __align__(16) float sW[KH * HID];          // 20 KB
    __shared__ __align__(16) float sX[G1_ROWS * KHP];     // 21.5 KB (41.5 KB)
    const int t = threadIdx.x;
    const int row0 = blockIdx.x * G1_ROWS;

    for (int i = t; i < KH * HID; i += 256) sW[i] = W1[i];
    for (int i = t; i < G1_ROWS * INC; i += 256) {
        int r = i >> 6, c = i & 63;
        int gr = row0 + r;
        sX[r * KHP + c] = (gr < GN) ? x[gr * INC + c] : 0.0f;
    }
    for (int i = t; i < G1_ROWS * POSC; i += 256) {
        int r = i >> 4, c = i & 15;
        int gr = row0 + r;
        sX[r * KHP + INC + c] = (gr < GN) ? pos[gr * POSC + c] : 0.0f;
    }
    __syncthreads();

    const int tx = t & 15;   // 16 col groups x 4 = 64 cols
    const int ty = t >> 4;   // 16 row groups x 4 = 64 rows
    float acc[4][4];
#pragma unroll
    for (int r = 0; r < 4; r++)
#pragma unroll
        for (int c = 0; c < 4; c++) acc[r][c] = 0.0f;

    for (int k0 = 0; k0 < KH; k0 += 4) {
        float4 xv[4];
#pragma unroll
        for (int r = 0; r < 4; r++)
            xv[r] = *(const float4*)&sX[(ty * 4 + r) * KHP + k0];
#pragma unroll
        for (int kk = 0; kk < 4; kk++) {
            float4 w = *(const float4*)&sW[(k0 + kk) * HID + tx * 4];
#pragma unroll
            for (int r = 0; r < 4; r++) {
                float xs = f4c(xv[r], kk);
                acc[r][0] += xs * w.x; acc[r][1] += xs * w.y;
                acc[r][2] += xs * w.z; acc[r][3] += xs * w.w;
            }
        }
    }
#pragma unroll
    for (int r = 0; r < 4; r++) {
        int gr = row0 + ty * 4 + r;
        if (gr < GN)
            *(float4*)&hw1[gr * HID + tx * 4] =
                make_float4(acc[r][0], acc[r][1], acc[r][2], acc[r][3]);
    }
}

// ---------------- layer-1 agg init: agg1 = b1 + hw1 * dinv^2 ----------------
__global__ void k_init1(const float4* __restrict__ hw, float4* __restrict__ out,
                        const float* __restrict__ b1, const float* __restrict__ dinv)
{
    int i = blockIdx.x * blockDim.x + threadIdx.x;
    if (i >= GN * 16) return;
    int node = i >> 4, q = i & 15;
    float dv = __ldg(&dinv[node]);
    float s = dv * dv;
    float4 v = __ldg(&hw[i]);
    float4 b = __ldg(&((const float4*)b1)[q]);
    out[i] = make_float4(b.x + v.x * s, b.y + v.y * s,
                         b.z + v.z * s, b.w + v.w * s);
}

// ---------------- GEMM 2: hw2 = relu(agg1) @ W2  (K=64, Nout=32) ------------
// 128 rows per block, 256 threads. Thread: 4 rows x 4 cols, k-blocks of 4.
// Epilogue writes z = b2 + hw2 * dinv^2 (dinv ready by now).
#define HIDP 68          // padded row stride (mult of 4; 68 mod 32 banks = 4)
#define G2_ROWS 128
__global__ __launch_bounds__(256) void k_gemm2(
    const float* __restrict__ h, const float* __restrict__ W2,
    const float* __restrict__ b2, const float* __restrict__ dinv,
    float* __restrict__ hw2, float* __restrict__ z)
{
    __shared__ __align__(16) float sW[HID * OUTC];        // 8 KB
    __shared__ __align__(16) float sH[G2_ROWS * HIDP];    // 34.8 KB (42.8 KB)
    const int t = threadIdx.x;
    const int row0 = blockIdx.x * G2_ROWS;

    for (int i = t; i < HID * OUTC; i += 256) sW[i] = W2[i];
    for (int i = t; i < G2_ROWS * HID; i += 256) {
        int r = i >> 6, c = i & 63;
        int gr = row0 + r;
        float v = (gr < GN) ? h[gr * HID + c] : 0.0f;
        sH[r * HIDP + c] = v > 0.0f ? v : 0.0f;       // fused ReLU
    }
    __syncthreads();

    const int tx = t & 7;    // 8 col groups x 4 = 32 cols
    const int ty = t >> 3;   // 32 row groups x 4 = 128 rows
    float acc[4][4];
#pragma unroll
    for (int r = 0; r < 4; r++)
#pragma unroll
        for (int c = 0; c < 4; c++) acc[r][c] = 0.0f;

    for (int k0 = 0; k0 < HID; k0 += 4) {
        float4 hv[4];
#pragma unroll
        for (int r = 0; r < 4; r++)
            hv[r] = *(const float4*)&sH[(ty * 4 + r) * HIDP + k0];
#pragma unroll
        for (int kk = 0; kk < 4; kk++) {
            float4 w = *(const float4*)&sW[(k0 + kk) * OUTC + tx * 4];
#pragma unroll
            for (int r = 0; r < 4; r++) {
                float hs = f4c(hv[r], kk);
                acc[r][0] += hs * w.x; acc[r][1] += hs * w.y;
                acc[r][2] += hs * w.z; acc[r][3] += hs * w.w;
            }
        }
    }

    float4 b = __ldg(&((const float4*)b2)[tx]);
#pragma unroll
    for (int r = 0; r < 4; r++) {
        int gr = row0 + ty * 4 + r;
        if (gr < GN) {
            float dv = __ldg(&dinv[gr]);
            float s = dv * dv;
            *(float4*)&hw2[gr * OUTC + tx * 4] =
                make_float4(acc[r][0], acc[r][1], acc[r][2], acc[r][3]);
            *(float4*)&z[gr * OUTC + tx * 4] =
                make_float4(b.x + acc[r][0] * s, b.y + acc[r][1] * s,
                            b.z + acc[r][2] * s, b.w + acc[r][3] * s);
        }
    }
}

// ---------------- segmented edge aggregation over dst-sorted list ------------
template <int LOGQ, int SB>   // LOGQ=4 (64 feats) SB=256 ; LOGQ=3 (32) SB=512
__global__ __launch_bounds__(256) void k_agg_seg(
    const float4* __restrict__ vals, float4* __restrict__ out,
    const int* __restrict__ csrc, const int* __restrict__ cdst,
    const float* __restrict__ cnrm)
{
    __shared__ int   ssrc[SB];
    __shared__ int   sdst[SB];
    __shared__ float snrm[SB];
    const int t = threadIdx.x;
    const int s0 = blockIdx.x * SB;
    for (int i = t; i < SB; i += 256) {
        ssrc[i] = csrc[s0 + i];
        sdst[i] = cdst[s0 + i];
        snrm[i] = cnrm[s0 + i];
    }
    __syncthreads();

    const int q    = t & ((1 << LOGQ) - 1);
    const int base = (t >> LOGQ) * 16;          // window of 16 slots

    int cur = sdst[base];
    float ax = 0.0f, ay = 0.0f, az = 0.0f, aw = 0.0f;
#pragma unroll
    for (int j = 0; j < 16; j++) {
        int sd = sdst[base + j];
        if (sd != cur) {
            float4* p = &out[(cur << LOGQ) + q];
            asm volatile("red.global.add.v4.f32 [%0], {%1,%2,%3,%4};"
                         :: "l"(p), "f"(ax), "f"(ay), "f"(az), "f"(aw)
                         : "memory");
            ax = ay = az = aw = 0.0f;
            cur = sd;
        }
        float nm = snrm[base + j];
        float4 v = __ldg(&vals[(ssrc[base + j] << LOGQ) + q]);
        ax += v.x * nm; ay += v.y * nm; az += v.z * nm; aw += v.w * nm;
    }
    float4* p = &out[(cur << LOGQ) + q];
    asm volatile("red.global.add.v4.f32 [%0], {%1,%2,%3,%4};"
                 :: "l"(p), "f"(ax), "f"(ay), "f"(az), "f"(aw)
                 : "memory");
}

// ---------------- link head: wa = z.Wl[0:32], wb = z.Wl[32:64] --------------
__global__ void k_wab(const float* __restrict__ z, const float* __restrict__ Wl,
                      float* __restrict__ wa, float* __restrict__ wb)
{
    __shared__ float sWl[2 * OUTC];
    int t = threadIdx.x;
    if (t < 2 * OUTC) sWl[t] = Wl[t];
    __syncthreads();
    int i = blockIdx.x * blockDim.x + t;
    if (i >= GN) return;
    const float4* zr = (const float4*)&z[i * OUTC];
    float a = 0.0f, b = 0.0f;
#pragma unroll
    for (int q = 0; q < OUTC / 4; q++) {
        float4 v = zr[q];
        a += v.x * sWl[q*4+0] + v.y * sWl[q*4+1] + v.z * sWl[q*4+2] + v.w * sWl[q*4+3];
        b += v.x * sWl[OUTC+q*4+0] + v.y * sWl[OUTC+q*4+1]
           + v.z * sWl[OUTC+q*4+2] + v.w * sWl[OUTC+q*4+3];
    }
    wa[i] = a; wb[i] = b;
}

__global__ void k_pred(const float* __restrict__ wa, const float* __restrict__ wb,
                       const int* __restrict__ sl, const int* __restrict__ dl,
                       const float* __restrict__ bl, float* __restrict__ pred)
{
    int i = blockIdx.x * blockDim.x + threadIdx.x;
    if (i >= GEL) return;
    pred[i] = wa[__ldg(&sl[i])] + wb[__ldg(&dl[i])] + bl[0];
}

// ---------------- launch -----------------------------------------------------
extern "C" void kernel_launch(void* const* d_in, const int* in_sizes, int n_in,
                              void* d_out, int out_size)
{
    const float* x    = (const float*)d_in[0];
    const float* pos  = (const float*)d_in[1];
    const float* W1   = (const float*)d_in[2];
    const float* b1   = (const float*)d_in[3];
    const float* W2   = (const float*)d_in[4];
    const float* b2   = (const float*)d_in[5];
    const float* Wl   = (const float*)d_in[6];
    const float* bl   = (const float*)d_in[7];
    const int*   ei   = (const int*)d_in[8];   // [2, E]: src row then dst row
    const int*   eli  = (const int*)d_in[9];   // [2, EL]

    const int* src = ei;
    const int* dst = ei + GE;
    const int* sl  = eli;
    const int* dl  = eli + GEL;

    float* z    = (float*)d_out;               // [N, OUTC]
    float* pred = z + (size_t)GN * OUTC;       // [EL]

    float *dinv, *hw1, *agg1, *hw2, *wa, *wb, *cnrm;
    int *cnt, *cur, *bsum, *bscan, *csrc, *cdst;
    cudaGetSymbolAddress((void**)&dinv,  g_dinv);
    cudaGetSymbolAddress((void**)&hw1,   g_hw1);
    cudaGetSymbolAddress((void**)&agg1,  g_agg1);
    cudaGetSymbolAddress((void**)&hw2,   g_hw2);
    cudaGetSymbolAddress((void**)&wa,    g_wa);
    cudaGetSymbolAddress((void**)&wb,    g_wb);
    cudaGetSymbolAddress((void**)&cnt,   g_cnt);
    cudaGetSymbolAddress((void**)&cur,   g_cur);
    cudaGetSymbolAddress((void**)&bsum,  g_bsum);
    cudaGetSymbolAddress((void**)&bscan, g_bscan);
    cudaGetSymbolAddress((void**)&csrc,  g_csrc);
    cudaGetSymbolAddress((void**)&cdst,  g_cdst);
    cudaGetSymbolAddress((void**)&cnrm,  g_cnrm);

    const int B = 256;

    // Fork: CSR build on a side stream, gemm1 (independent) on the main stream.
    // (Exact 2-event topology that passed in rounds 9/11/13.)
    cudaStream_t side;
    cudaStreamCreateWithFlags(&side, cudaStreamNonBlocking);
    cudaEvent_t evF, evJ;
    cudaEventCreateWithFlags(&evF, cudaEventDisableTiming);
    cudaEventCreateWithFlags(&evJ, cudaEventDisableTiming);

    cudaEventRecord(evF, 0);
    cudaStreamWaitEvent(side, evF, 0);

    // ---- side stream: histogram -> scan(+dinv) -> dst-sorted fill
    k_zero_cnt<<<(GN + B - 1) / B, B, 0, side>>>(cnt);
    k_hist<<<(GE + B - 1) / B, B, 0, side>>>(dst, cnt);
    k_scan_local<<<NB, 256, 0, side>>>(cnt, cur, bsum);
    k_scan_bsum<<<1, 128, 0, side>>>(bsum, bscan);
    k_scan_add<<<NB, 256, 0, side>>>(cur, bscan, cnt, dinv);
    k_fill<<<(GE + B - 1) / B, B, 0, side>>>(src, dst, dinv, cur, csrc, cdst, cnrm);
    cudaEventRecord(evJ, side);                 // build done

    // ---- main stream: gemm1 runs concurrently with the build
    k_gemm1<<<(GN + G1_ROWS - 1) / G1_ROWS, 256>>>(x, pos, W1, hw1);

    // Join: everything below needs the build outputs.
    cudaStreamWaitEvent(0, evJ, 0);

    // ---- layer 1
    k_init1<<<(GN * 16 + B - 1) / B, B>>>((const float4*)hw1, (float4*)agg1, b1, dinv);
    k_agg_seg<4, 256><<<GE / 256, 256>>>((const float4*)hw1, (float4*)agg1,
                                         csrc, cdst, cnrm);

    // ---- layer 2 (ReLU fused into gemm2 smem load; z init fused in epilogue)
    k_gemm2<<<(GN + G2_ROWS - 1) / G2_ROWS, 256>>>(agg1, W2, b2, dinv, hw2, z);
    k_agg_seg<3, 512><<<GE / 512, 256>>>((const float4*)hw2, (float4*)z,
                                         csrc, cdst, cnrm);

    // ---- link-prediction head: pred = z[s].Wl_top + z[d].Wl_bot + bl
    k_wab<<<(GN + B - 1) / B, B>>>(z, Wl, wa, wb);
    k_pred<<<(GEL + B - 1) / B, B>>>(wa, wb, sl, dl, bl, pred);
}